// round 15
// baseline (speedup 1.0000x reference)
#include <cuda_runtime.h>
#include <cuda_fp16.h>
#include <cstdint>

#define Bq 4096
#define Iq 256
#define Oq 256
#define NCH 260                 // 256 fourier chunks + 4 base chunks (K=64 each)
#define NSPLIT 4
#define CPS 65                  // chunks per split
// stage layout: A 16K | W 32K
#define AHo 0
#define WHo 16384
#define STG 49152
#define GSMEM (2*STG + 256)

// ---------- scratch (__device__ globals only) ----------
__device__ float g_c1[(size_t)Iq * Bq];
__device__ float g_s1[(size_t)Iq * Bq];
__device__ float g_c17[(size_t)Iq * Bq];
__device__ float g_s17[(size_t)Iq * Bq];
__device__ __align__(16) unsigned short g_bh[(size_t)Bq * Iq];       // silu fp16 [b][i]
__device__ __align__(16) unsigned short g_Wh[(size_t)NCH * Oq * 64]; // fp16 [chunk][j][slot]
__device__ __align__(16) float g_part[(size_t)NSPLIT * Bq * Oq];     // split-K partials
__device__ unsigned int g_cnt[Bq / 128];                             // per-b-tile arrival counters (start 0, return to 0)

// ---------- helpers ----------
__device__ __forceinline__ uint32_t smem_u32(const void* p) {
    uint32_t a;
    asm("{ .reg .u64 t; cvta.to.shared.u64 t, %1; cvt.u32.u64 %0, t; }" : "=r"(a) : "l"(p));
    return a;
}
__device__ __forceinline__ uint32_t swz(uint32_t off) { return off ^ ((off >> 3) & 0x70); }
__device__ __forceinline__ uint32_t h2pack(float a, float b) {  // a->low half
    uint32_t r;
    asm("cvt.rn.f16x2.f32 %0, %1, %2;" : "=r"(r) : "f"(b), "f"(a));
    return r;
}
__device__ __forceinline__ void rot(float& c, float& s, float c1, float s1) {
    float t = fmaf(c, c1, -(s * s1));
    float u = fmaf(s, c1, c * s1);
    c = t; s = u;
}

#define STS128(a, v) asm volatile("st.shared.v4.b32 [%0], {%1,%2,%3,%4};" \
    :: "r"(a), "r"((v).x), "r"((v).y), "r"((v).z), "r"((v).w) : "memory")
#define LDSM4(r, addr) asm volatile( \
    "ldmatrix.sync.aligned.m8n8.x4.shared.b16 {%0,%1,%2,%3}, [%4];" \
    : "=r"((r)[0]), "=r"((r)[1]), "=r"((r)[2]), "=r"((r)[3]) : "r"(addr))
#define HMMA(d, a0v, a1v, a2v, a3v, b0v, b1v) asm volatile( \
    "mma.sync.aligned.m16n8k16.row.col.f32.f16.f16.f32 " \
    "{%0,%1,%2,%3}, {%4,%5,%6,%7}, {%8,%9}, {%0,%1,%2,%3};" \
    : "+f"((d)[0]), "+f"((d)[1]), "+f"((d)[2]), "+f"((d)[3]) \
    : "r"(a0v), "r"(a1v), "r"(a2v), "r"(a3v), "r"(b0v), "r"(b1v))
#define CPASYNC16(dst, src) asm volatile( \
    "cp.async.ca.shared.global [%0], [%1], 16;" :: "r"(dst), "l"(src))
#define CPCOMMIT() asm volatile("cp.async.commit_group;" ::: "memory")
#define CPWAIT0()  asm volatile("cp.async.wait_group 0;" ::: "memory")

// ---------- kernel 1: sincos/silu transform ----------
__global__ void kan_xform(const float* __restrict__ x) {
    __shared__ float tx[32][33];
    int b0 = blockIdx.x * 32, i0 = blockIdx.y * 32;
    int tid = threadIdx.x;
#pragma unroll
    for (int it = 0; it < 4; ++it) {
        int idx = tid + it * 256;
        int bb = idx >> 5, ii = idx & 31;
        float v = x[(size_t)(b0 + bb) * Iq + i0 + ii];
        tx[bb][ii] = v;
        float sl = v / (1.0f + __expf(-v));   // bounded arg: safe fast path
        __half h = __float2half_rn(sl);
        g_bh[(size_t)(b0 + bb) * Iq + i0 + ii] = *reinterpret_cast<unsigned short*>(&h);
    }
    __syncthreads();
#pragma unroll
    for (int it = 0; it < 4; ++it) {
        int idx = tid + it * 256;
        int ii = idx >> 5, bb = idx & 31;
        float v = tx[bb][ii];
        float s, c;
        sincosf(v, &s, &c);                   // precise: seeds feed 32-step recurrence
        size_t o = (size_t)(i0 + ii) * Bq + b0 + bb;
        g_c1[o] = c; g_s1[o] = s;
        sincosf(17.0f * v, &s, &c);
        g_c17[o] = c; g_s17[o] = s;
    }
}

// ---------- kernel 2: fold weights -> fp16 (coalesced; lanes 0-15 cos, 16-31 sin) ----------
__global__ void kan_prep(const float* __restrict__ fc, const float* __restrict__ mask,
                         const float* __restrict__ sb, const float* __restrict__ sf) {
    int blk = blockIdx.x;
    if (blk < Iq) {
        int i = blk;
        int w = threadIdx.x >> 5, lane = threadIdx.x & 31;
        int half = lane >> 4;                 // 0 = cos (fc[0]), 1 = sin (fc[1])
        int kk = lane & 15;                   // k-pair index 0..15
        unsigned short* dst = g_Wh + (size_t)i * Oq * 64;
        const float* fbase = fc + (size_t)half * Oq * Iq * 32;
#pragma unroll 4
        for (int jt = 0; jt < 32; ++jt) {
            int j = w * 32 + jt;
            float m = mask[i * Oq + j];
            float wf = sf[i * Oq + j] * m;
            float2 v2 = *reinterpret_cast<const float2*>(
                fbase + ((size_t)j * Iq + i) * 32 + 2 * kk);
            uint32_t p = h2pack(wf * v2.x, wf * v2.y);
            *reinterpret_cast<uint32_t*>(dst + (size_t)j * 64 + half * 32 + 2 * kk) = p;
        }
    } else {
        int cb = blk - Iq, j = threadIdx.x;
        unsigned short* dh = g_Wh + ((size_t)blk * Oq + j) * 64;
        for (int g = 0; g < 8; ++g) {
            uint4 vh;
            uint32_t* ph = &vh.x;
            for (int e = 0; e < 4; ++e) {
                int s0 = g * 8 + 2 * e;
                int ia = cb * 64 + s0, ib = ia + 1;
                float w0 = mask[ia * Oq + j] * sb[ia * Oq + j];
                float w1 = mask[ib * Oq + j] * sb[ib * Oq + j];
                ph[e] = h2pack(w0, w1);
            }
            *reinterpret_cast<uint4*>(dh + g * 8) = vh;
        }
    }
}

// ---------- kernel 3: HMMA fused GEMM, split-K, fused last-CTA reduction ----------
__global__ void __launch_bounds__(512, 1)
kan_gemm(const float* __restrict__ bias, float* __restrict__ out) {
    extern __shared__ char smem[];
    const uint32_t sbase = (smem_u32(smem) + 127) & ~127u;

    const int tid = threadIdx.x, lane = tid & 31, wid = tid >> 5;
    const int wm = wid & 3, wn = wid >> 2;          // warp grid 4m x 4n (n=64 each)
    const int b0 = blockIdx.x * 128;
    const int spl = blockIdx.y;
    const int c0 = spl * CPS;

    const int gm = (tid & 255) >> 1, gh = tid & 1;  // A-gen (tid<256 only): row, half

    float acc[2][8][4];
#pragma unroll
    for (int mt = 0; mt < 2; ++mt)
#pragma unroll
        for (int nf = 0; nf < 8; ++nf)
#pragma unroll
            for (int e = 0; e < 4; ++e) acc[mt][nf][e] = 0.0f;

    const uint32_t arow = (uint32_t)gm * 128;
    const uint32_t aoff = (uint32_t)(wm * 32 + (lane & 15)) * 128 + (lane >> 4) * 16;
    const uint32_t boff = (uint32_t)(wn * 64 + (lane & 7) + ((lane >> 4) << 3)) * 128
                        + ((lane >> 3) & 1) * 16;

    auto stageW = [&](int cn, uint32_t wB) {
        const unsigned short* src = g_Wh + (size_t)cn * Oq * 64;
#pragma unroll
        for (int g = 0; g < 4; ++g) {
            int idx = tid + g * 512;
            int jj = idx >> 3, p = idx & 7;
            CPASYNC16(wB + swz((uint32_t)jj * 128 + p * 16),
                      src + (size_t)jj * 64 + p * 8);
        }
    };

    auto genA = [&](int cn, uint32_t aBase, float c1s, float s1s, float ccs, float sss) {
        uint32_t aH[16];
        if (cn < Iq) {
            float cc = ccs, ss = sss;
#pragma unroll
            for (int p = 0; p < 8; ++p) {
                float ca = cc, sa = ss; rot(cc, ss, c1s, s1s);
                float cb = cc, sb2 = ss; rot(cc, ss, c1s, s1s);
                aH[p]     = h2pack(ca, cb);
                aH[8 + p] = h2pack(sa, sb2);
            }
        } else {
            int cb = cn - Iq;
            const unsigned short* ph = g_bh + (size_t)(b0 + gm) * Iq + cb * 64;
            uint4 v;
            v = *(const uint4*)(ph + 16 * gh);          aH[0]=v.x; aH[1]=v.y; aH[2]=v.z; aH[3]=v.w;
            v = *(const uint4*)(ph + 16 * gh + 8);      aH[4]=v.x; aH[5]=v.y; aH[6]=v.z; aH[7]=v.w;
            v = *(const uint4*)(ph + 32 + 16 * gh);     aH[8]=v.x; aH[9]=v.y; aH[10]=v.z; aH[11]=v.w;
            v = *(const uint4*)(ph + 32 + 16 * gh + 8); aH[12]=v.x; aH[13]=v.y; aH[14]=v.z; aH[15]=v.w;
        }
        STS128(aBase + swz(arow + 32 * gh),           make_uint4(aH[0], aH[1], aH[2], aH[3]));
        STS128(aBase + swz(arow + 32 * gh + 16),      make_uint4(aH[4], aH[5], aH[6], aH[7]));
        STS128(aBase + swz(arow + 64 + 32 * gh),      make_uint4(aH[8], aH[9], aH[10], aH[11]));
        STS128(aBase + swz(arow + 64 + 32 * gh + 16), make_uint4(aH[12], aH[13], aH[14], aH[15]));
    };

    // ---- prologue: chunk c0 into stage 0 ----
    {
        stageW(c0, sbase + WHo);
        CPCOMMIT();
        if (tid < 256) {
            float c1s = 0.f, s1s = 0.f, ccs = 0.f, sss = 0.f;
            if (c0 < Iq) {
                size_t gb = (size_t)c0 * Bq + b0 + gm;
                c1s = g_c1[gb]; s1s = g_s1[gb];
                if (gh) { ccs = g_c17[gb]; sss = g_s17[gb]; }
                else    { ccs = c1s;       sss = s1s; }
            }
            genA(c0, sbase + AHo, c1s, s1s, ccs, sss);
        }
        CPWAIT0();
    }

    for (int ci = 0; ci < CPS; ++ci) {
        const int c = c0 + ci;
        const uint32_t st = sbase + (ci & 1) * STG;

        __syncthreads();   // stage (ci&1) ready; opposite stage free

        const int cn = c + 1;
        const bool more = (ci + 1 < CPS);
        float c1s = 0.f, s1s = 0.f, ccs = 0.f, sss = 0.f;
        if (more) {
            const uint32_t sn = sbase + ((ci + 1) & 1) * STG;
            stageW(cn, sn + WHo);            // async, no regs held
            CPCOMMIT();
            if (tid < 256 && cn < Iq) {
                size_t gb = (size_t)cn * Bq + b0 + gm;
                c1s = g_c1[gb]; s1s = g_s1[gb];
                if (gh) { ccs = g_c17[gb]; sss = g_s17[gb]; }
                else    { ccs = c1s;       sss = s1s; }
            }
        }

        // ---- MMA on chunk c: per kk, batch all LDSM then all HMMA ----
        const uint32_t aB = st + AHo, wB = st + WHo;
#pragma unroll
        for (int kk = 0; kk < 4; ++kk) {
            uint32_t a0[4], a1[4], w[4][4];
            LDSM4(a0, aB + swz(aoff + kk * 32));
            LDSM4(a1, aB + swz(aoff + 2048 + kk * 32));
#pragma unroll
            for (int g = 0; g < 4; ++g)
                LDSM4(w[g], wB + swz(boff + (uint32_t)g * 2048 + kk * 32));
#pragma unroll
            for (int g = 0; g < 4; ++g) {
                HMMA(acc[0][2 * g],     a0[0], a0[1], a0[2], a0[3], w[g][0], w[g][1]);
                HMMA(acc[0][2 * g + 1], a0[0], a0[1], a0[2], a0[3], w[g][2], w[g][3]);
                HMMA(acc[1][2 * g],     a1[0], a1[1], a1[2], a1[3], w[g][0], w[g][1]);
                HMMA(acc[1][2 * g + 1], a1[0], a1[1], a1[2], a1[3], w[g][2], w[g][3]);
            }
        }

        // ---- generate + STS A(c+1) into opposite stage ----
        if (more && tid < 256) {
            genA(cn, sbase + ((ci + 1) & 1) * STG + AHo, c1s, s1s, ccs, sss);
        }
        CPWAIT0();
    }

    // ---- epilogue: write fp32 partials ----
    float* pp = g_part + (size_t)spl * Bq * Oq;
#pragma unroll
    for (int mt = 0; mt < 2; ++mt) {
#pragma unroll
        for (int nf = 0; nf < 8; ++nf) {
            int row = b0 + wm * 32 + mt * 16 + (lane >> 2);
            int col = wn * 64 + nf * 8 + 2 * (lane & 3);
            *reinterpret_cast<float2*>(pp + (size_t)row * Oq + col) =
                make_float2(acc[mt][nf][0], acc[mt][nf][1]);
            *reinterpret_cast<float2*>(pp + (size_t)(row + 8) * Oq + col) =
                make_float2(acc[mt][nf][2], acc[mt][nf][3]);
        }
    }

    // ---- fused split-K reduction: last CTA of this b-tile reduces all 4 partials ----
    __threadfence();
    __syncthreads();
    __shared__ unsigned int s_old;
    if (tid == 0) s_old = atomicAdd(&g_cnt[blockIdx.x], 1);
    __syncthreads();
    if (s_old == NSPLIT - 1) {
        if (tid == 0) g_cnt[blockIdx.x] = 0;   // restore for next graph replay
        const size_t n4 = (size_t)Bq * Oq / 4;
        const float4* p0 = (const float4*)g_part + ((size_t)b0 * Oq) / 4;
        float4* o4 = (float4*)out + ((size_t)b0 * Oq) / 4;
        const float4* b4 = (const float4*)bias;
#pragma unroll
        for (int it = 0; it < 16; ++it) {
            int idx = tid + it * 512;          // 0..8191 (128 rows x 64 float4)
            float4 a = p0[idx];
            float4 b = p0[idx + n4];
            float4 c = p0[idx + 2 * n4];
            float4 d = p0[idx + 3 * n4];
            float4 bv = b4[idx & 63];
            float4 r;
            r.x = a.x + b.x + c.x + d.x + bv.x;
            r.y = a.y + b.y + c.y + d.y + bv.y;
            r.z = a.z + b.z + c.z + d.z + bv.z;
            r.w = a.w + b.w + c.w + d.w + bv.w;
            o4[idx] = r;
        }
    }
}

extern "C" void kernel_launch(void* const* d_in, const int* in_sizes, int n_in,
                              void* d_out, int out_size) {
    const float* x    = (const float*)d_in[0];
    const float* fc   = (const float*)d_in[1];
    const float* bias = (const float*)d_in[2];
    const float* mask = (const float*)d_in[3];
    const float* sb   = (const float*)d_in[4];
    const float* sf   = (const float*)d_in[5];
    float* out = (float*)d_out;

    cudaFuncSetAttribute(kan_gemm, cudaFuncAttributeMaxDynamicSharedMemorySize, GSMEM);

    kan_xform<<<dim3(Bq / 32, Iq / 32), 256>>>(x);
    kan_prep<<<NCH, 256>>>(fc, mask, sb, sf);
    kan_gemm<<<dim3(Bq / 128, NSPLIT), 512, GSMEM>>>(bias, out);
}

// round 16
// speedup vs baseline: 1.0634x; 1.0634x over previous
#include <cuda_runtime.h>
#include <cuda_fp16.h>
#include <cstdint>

#define Bq 4096
#define Iq 256
#define Oq 256
#define NCH 260                 // 256 fourier chunks + 4 base chunks (K=64 each)
#define NSPLIT 4
#define CPS 65                  // chunks per split
// stage layout: A 16K | W 32K
#define AHo 0
#define WHo 16384
#define STG 49152
#define GSMEM (2*STG + 256)

// ---------- scratch (__device__ globals only) ----------
__device__ float g_c1[(size_t)Iq * Bq];
__device__ float g_s1[(size_t)Iq * Bq];
__device__ float g_c17[(size_t)Iq * Bq];
__device__ float g_s17[(size_t)Iq * Bq];
__device__ __align__(16) unsigned short g_bh[(size_t)Bq * Iq];       // silu fp16 [b][i]
__device__ __align__(16) unsigned short g_Wh[(size_t)NCH * Oq * 64]; // fp16 [chunk][j][slot]
__device__ __align__(16) float g_part[(size_t)NSPLIT * Bq * Oq];     // split-K partials

// ---------- helpers ----------
__device__ __forceinline__ uint32_t smem_u32(const void* p) {
    uint32_t a;
    asm("{ .reg .u64 t; cvta.to.shared.u64 t, %1; cvt.u32.u64 %0, t; }" : "=r"(a) : "l"(p));
    return a;
}
__device__ __forceinline__ uint32_t swz(uint32_t off) { return off ^ ((off >> 3) & 0x70); }
__device__ __forceinline__ uint32_t h2pack(float a, float b) {  // a->low half
    uint32_t r;
    asm("cvt.rn.f16x2.f32 %0, %1, %2;" : "=r"(r) : "f"(b), "f"(a));
    return r;
}
__device__ __forceinline__ void rot(float& c, float& s, float c1, float s1) {
    float t = fmaf(c, c1, -(s * s1));
    float u = fmaf(s, c1, c * s1);
    c = t; s = u;
}

#define STS128(a, v) asm volatile("st.shared.v4.b32 [%0], {%1,%2,%3,%4};" \
    :: "r"(a), "r"((v).x), "r"((v).y), "r"((v).z), "r"((v).w) : "memory")
#define LDSM4(r, addr) asm volatile( \
    "ldmatrix.sync.aligned.m8n8.x4.shared.b16 {%0,%1,%2,%3}, [%4];" \
    : "=r"((r)[0]), "=r"((r)[1]), "=r"((r)[2]), "=r"((r)[3]) : "r"(addr))
#define HMMA(d, a0v, a1v, a2v, a3v, b0v, b1v) asm volatile( \
    "mma.sync.aligned.m16n8k16.row.col.f32.f16.f16.f32 " \
    "{%0,%1,%2,%3}, {%4,%5,%6,%7}, {%8,%9}, {%0,%1,%2,%3};" \
    : "+f"((d)[0]), "+f"((d)[1]), "+f"((d)[2]), "+f"((d)[3]) \
    : "r"(a0v), "r"(a1v), "r"(a2v), "r"(a3v), "r"(b0v), "r"(b1v))
#define CPASYNC16(dst, src) asm volatile( \
    "cp.async.ca.shared.global [%0], [%1], 16;" :: "r"(dst), "l"(src))
#define CPCOMMIT() asm volatile("cp.async.commit_group;" ::: "memory")
#define CPWAIT0()  asm volatile("cp.async.wait_group 0;" ::: "memory")

// ---------- kernel 1: sincos/silu transform ----------
// c17/s17 derived from precise sincos(x) via 4 angle doublings + 1 rotation:
// phase error ~16 * 1ulp ~ 5e-6 rad, negligible vs fp16 quantization (4.9e-4).
__global__ void kan_xform(const float* __restrict__ x) {
    __shared__ float tx[32][33];
    int b0 = blockIdx.x * 32, i0 = blockIdx.y * 32;
    int tid = threadIdx.x;
#pragma unroll
    for (int it = 0; it < 4; ++it) {
        int idx = tid + it * 256;
        int bb = idx >> 5, ii = idx & 31;
        float v = x[(size_t)(b0 + bb) * Iq + i0 + ii];
        tx[bb][ii] = v;
        float sl = v / (1.0f + __expf(-v));   // bounded arg: safe fast path
        __half h = __float2half_rn(sl);
        g_bh[(size_t)(b0 + bb) * Iq + i0 + ii] = *reinterpret_cast<unsigned short*>(&h);
    }
    __syncthreads();
#pragma unroll
    for (int it = 0; it < 4; ++it) {
        int idx = tid + it * 256;
        int ii = idx >> 5, bb = idx & 31;
        float v = tx[bb][ii];
        float s1, c1;
        sincosf(v, &s1, &c1);                 // precise seed
        size_t o = (size_t)(i0 + ii) * Bq + b0 + bb;
        g_c1[o] = c1; g_s1[o] = s1;
        // 4 doublings: (c,s) -> (2c^2-1, 2sc) gives cos/sin(16x)
        float c = c1, s = s1;
#pragma unroll
        for (int d = 0; d < 4; ++d) {
            float t = 2.0f * c;
            float sn = t * s;                 // 2sc (old c)
            c = fmaf(t, c, -1.0f);            // 2c^2 - 1
            s = sn;
        }
        // rotate by x: 17x = 16x + x
        float c17 = fmaf(c, c1, -(s * s1));
        float s17 = fmaf(s, c1, c * s1);
        g_c17[o] = c17; g_s17[o] = s17;
    }
}

// ---------- kernel 2: fold weights -> fp16 (coalesced; lanes 0-15 cos, 16-31 sin) ----------
__global__ void kan_prep(const float* __restrict__ fc, const float* __restrict__ mask,
                         const float* __restrict__ sb, const float* __restrict__ sf) {
    int blk = blockIdx.x;
    if (blk < Iq) {
        int i = blk;
        int w = threadIdx.x >> 5, lane = threadIdx.x & 31;
        int half = lane >> 4;                 // 0 = cos (fc[0]), 1 = sin (fc[1])
        int kk = lane & 15;                   // k-pair index 0..15
        unsigned short* dst = g_Wh + (size_t)i * Oq * 64;
        const float* fbase = fc + (size_t)half * Oq * Iq * 32;
#pragma unroll 4
        for (int jt = 0; jt < 32; ++jt) {
            int j = w * 32 + jt;
            float m = mask[i * Oq + j];
            float wf = sf[i * Oq + j] * m;
            float2 v2 = *reinterpret_cast<const float2*>(
                fbase + ((size_t)j * Iq + i) * 32 + 2 * kk);
            uint32_t p = h2pack(wf * v2.x, wf * v2.y);
            *reinterpret_cast<uint32_t*>(dst + (size_t)j * 64 + half * 32 + 2 * kk) = p;
        }
    } else {
        int cb = blk - Iq, j = threadIdx.x;
        unsigned short* dh = g_Wh + ((size_t)blk * Oq + j) * 64;
        for (int g = 0; g < 8; ++g) {
            uint4 vh;
            uint32_t* ph = &vh.x;
            for (int e = 0; e < 4; ++e) {
                int s0 = g * 8 + 2 * e;
                int ia = cb * 64 + s0, ib = ia + 1;
                float w0 = mask[ia * Oq + j] * sb[ia * Oq + j];
                float w1 = mask[ib * Oq + j] * sb[ib * Oq + j];
                ph[e] = h2pack(w0, w1);
            }
            *reinterpret_cast<uint4*>(dh + g * 8) = vh;
        }
    }
}

// ---------- kernel 3: HMMA fused GEMM, split-K, N=256, 512 threads ----------
__global__ void __launch_bounds__(512, 1)
kan_gemm(float* __restrict__ dummy) {
    extern __shared__ char smem[];
    const uint32_t sbase = (smem_u32(smem) + 127) & ~127u;

    const int tid = threadIdx.x, lane = tid & 31, wid = tid >> 5;
    const int wm = wid & 3, wn = wid >> 2;          // warp grid 4m x 4n (n=64 each)
    const int b0 = blockIdx.x * 128;
    const int spl = blockIdx.y;
    const int c0 = spl * CPS;

    const int gm = (tid & 255) >> 1, gh = tid & 1;  // A-gen (tid<256 only): row, half

    float acc[2][8][4];
#pragma unroll
    for (int mt = 0; mt < 2; ++mt)
#pragma unroll
        for (int nf = 0; nf < 8; ++nf)
#pragma unroll
            for (int e = 0; e < 4; ++e) acc[mt][nf][e] = 0.0f;

    const uint32_t arow = (uint32_t)gm * 128;
    const uint32_t aoff = (uint32_t)(wm * 32 + (lane & 15)) * 128 + (lane >> 4) * 16;
    const uint32_t boff = (uint32_t)(wn * 64 + (lane & 7) + ((lane >> 4) << 3)) * 128
                        + ((lane >> 3) & 1) * 16;

    auto stageW = [&](int cn, uint32_t wB) {
        const unsigned short* src = g_Wh + (size_t)cn * Oq * 64;
#pragma unroll
        for (int g = 0; g < 4; ++g) {
            int idx = tid + g * 512;
            int jj = idx >> 3, p = idx & 7;
            CPASYNC16(wB + swz((uint32_t)jj * 128 + p * 16),
                      src + (size_t)jj * 64 + p * 8);
        }
    };

    auto genA = [&](int cn, uint32_t aBase, float c1s, float s1s, float ccs, float sss) {
        uint32_t aH[16];
        if (cn < Iq) {
            float cc = ccs, ss = sss;
#pragma unroll
            for (int p = 0; p < 8; ++p) {
                float ca = cc, sa = ss; rot(cc, ss, c1s, s1s);
                float cb = cc, sb2 = ss; rot(cc, ss, c1s, s1s);
                aH[p]     = h2pack(ca, cb);
                aH[8 + p] = h2pack(sa, sb2);
            }
        } else {
            int cb = cn - Iq;
            const unsigned short* ph = g_bh + (size_t)(b0 + gm) * Iq + cb * 64;
            uint4 v;
            v = *(const uint4*)(ph + 16 * gh);          aH[0]=v.x; aH[1]=v.y; aH[2]=v.z; aH[3]=v.w;
            v = *(const uint4*)(ph + 16 * gh + 8);      aH[4]=v.x; aH[5]=v.y; aH[6]=v.z; aH[7]=v.w;
            v = *(const uint4*)(ph + 32 + 16 * gh);     aH[8]=v.x; aH[9]=v.y; aH[10]=v.z; aH[11]=v.w;
            v = *(const uint4*)(ph + 32 + 16 * gh + 8); aH[12]=v.x; aH[13]=v.y; aH[14]=v.z; aH[15]=v.w;
        }
        STS128(aBase + swz(arow + 32 * gh),           make_uint4(aH[0], aH[1], aH[2], aH[3]));
        STS128(aBase + swz(arow + 32 * gh + 16),      make_uint4(aH[4], aH[5], aH[6], aH[7]));
        STS128(aBase + swz(arow + 64 + 32 * gh),      make_uint4(aH[8], aH[9], aH[10], aH[11]));
        STS128(aBase + swz(arow + 64 + 32 * gh + 16), make_uint4(aH[12], aH[13], aH[14], aH[15]));
    };

    // ---- prologue: chunk c0 into stage 0 ----
    {
        stageW(c0, sbase + WHo);
        CPCOMMIT();
        if (tid < 256) {
            float c1s = 0.f, s1s = 0.f, ccs = 0.f, sss = 0.f;
            if (c0 < Iq) {
                size_t gb = (size_t)c0 * Bq + b0 + gm;
                c1s = g_c1[gb]; s1s = g_s1[gb];
                if (gh) { ccs = g_c17[gb]; sss = g_s17[gb]; }
                else    { ccs = c1s;       sss = s1s; }
            }
            genA(c0, sbase + AHo, c1s, s1s, ccs, sss);
        }
        CPWAIT0();
    }

    for (int ci = 0; ci < CPS; ++ci) {
        const int c = c0 + ci;
        const uint32_t st = sbase + (ci & 1) * STG;

        __syncthreads();   // stage (ci&1) ready; opposite stage free

        const int cn = c + 1;
        const bool more = (ci + 1 < CPS);
        float c1s = 0.f, s1s = 0.f, ccs = 0.f, sss = 0.f;
        if (more) {
            const uint32_t sn = sbase + ((ci + 1) & 1) * STG;
            stageW(cn, sn + WHo);            // async, no regs held
            CPCOMMIT();
            if (tid < 256 && cn < Iq) {
                size_t gb = (size_t)cn * Bq + b0 + gm;
                c1s = g_c1[gb]; s1s = g_s1[gb];
                if (gh) { ccs = g_c17[gb]; sss = g_s17[gb]; }
                else    { ccs = c1s;       sss = s1s; }
            }
        }

        // ---- MMA on chunk c: per kk, batch all LDSM then all HMMA ----
        const uint32_t aB = st + AHo, wB = st + WHo;
#pragma unroll
        for (int kk = 0; kk < 4; ++kk) {
            uint32_t a0[4], a1[4], w[4][4];
            LDSM4(a0, aB + swz(aoff + kk * 32));
            LDSM4(a1, aB + swz(aoff + 2048 + kk * 32));
#pragma unroll
            for (int g = 0; g < 4; ++g)
                LDSM4(w[g], wB + swz(boff + (uint32_t)g * 2048 + kk * 32));
#pragma unroll
            for (int g = 0; g < 4; ++g) {
                HMMA(acc[0][2 * g],     a0[0], a0[1], a0[2], a0[3], w[g][0], w[g][1]);
                HMMA(acc[0][2 * g + 1], a0[0], a0[1], a0[2], a0[3], w[g][2], w[g][3]);
                HMMA(acc[1][2 * g],     a1[0], a1[1], a1[2], a1[3], w[g][0], w[g][1]);
                HMMA(acc[1][2 * g + 1], a1[0], a1[1], a1[2], a1[3], w[g][2], w[g][3]);
            }
        }

        // ---- generate + STS A(c+1) into opposite stage ----
        if (more && tid < 256) {
            genA(cn, sbase + ((ci + 1) & 1) * STG + AHo, c1s, s1s, ccs, sss);
        }
        CPWAIT0();
    }

    // ---- epilogue: write fp32 partials ----
    float* pp = g_part + (size_t)spl * Bq * Oq;
#pragma unroll
    for (int mt = 0; mt < 2; ++mt) {
#pragma unroll
        for (int nf = 0; nf < 8; ++nf) {
            int row = b0 + wm * 32 + mt * 16 + (lane >> 2);
            int col = wn * 64 + nf * 8 + 2 * (lane & 3);
            *reinterpret_cast<float2*>(pp + (size_t)row * Oq + col) =
                make_float2(acc[mt][nf][0], acc[mt][nf][1]);
            *reinterpret_cast<float2*>(pp + (size_t)(row + 8) * Oq + col) =
                make_float2(acc[mt][nf][2], acc[mt][nf][3]);
        }
    }
}

// ---------- kernel 4: split-K reduce + bias ----------
__global__ void kan_reduce(const float* __restrict__ bias, float* __restrict__ out) {
    int idx = blockIdx.x * 256 + threadIdx.x;           // float4 index
    const float4* p0 = (const float4*)g_part;
    const size_t n4 = (size_t)Bq * Oq / 4;
    float4 a = p0[idx];
    float4 b = p0[n4 + idx];
    float4 c = p0[2 * n4 + idx];
    float4 d = p0[3 * n4 + idx];
    float4 bv = ((const float4*)bias)[idx & 63];
    float4 r;
    r.x = a.x + b.x + c.x + d.x + bv.x;
    r.y = a.y + b.y + c.y + d.y + bv.y;
    r.z = a.z + b.z + c.z + d.z + bv.z;
    r.w = a.w + b.w + c.w + d.w + bv.w;
    ((float4*)out)[idx] = r;
}

extern "C" void kernel_launch(void* const* d_in, const int* in_sizes, int n_in,
                              void* d_out, int out_size) {
    const float* x    = (const float*)d_in[0];
    const float* fc   = (const float*)d_in[1];
    const float* bias = (const float*)d_in[2];
    const float* mask = (const float*)d_in[3];
    const float* sb   = (const float*)d_in[4];
    const float* sf   = (const float*)d_in[5];
    float* out = (float*)d_out;

    cudaFuncSetAttribute(kan_gemm, cudaFuncAttributeMaxDynamicSharedMemorySize, GSMEM);

    kan_xform<<<dim3(Bq / 32, Iq / 32), 256>>>(x);
    kan_prep<<<NCH, 256>>>(fc, mask, sb, sf);
    kan_gemm<<<dim3(Bq / 128, NSPLIT), 512, GSMEM>>>(out);
    kan_reduce<<<Bq * Oq / 4 / 256, 256>>>(bias, out);
}